// round 16
// baseline (speedup 1.0000x reference)
#include <cuda_runtime.h>
#include <cstdint>

typedef unsigned long long u64;

#define N_INP   64
#define N_HID   512
#define BATCH   128
#define SEQ     1024
#define DT_C    0.042f
#define CSZ     16      // CTAs per cluster
#define BC      8       // batches per cluster (2 groups of 4)
#define HS      32      // hidden slice per CTA
#define THREADS 256
#define HYF_P   516     // hy_full row pitch (floats)

// W swizzle: quad gq of row k stored at slot gq ^ SWZ(k)
#define SWZ(k) (((k) ^ ((k) >> 3)) & 7)

struct __align__(16) Smem {
    float4 W[512 * 8];            // 65536 B  h2h[:,slice]
    float  hy_full[BC * HYF_P];   // 16512 B  all-gathered hy, [b][k]
    float  wrecv[2 * 16 * 4 * HS];// 16384 B  [g][src][b4][kin]
    float4 scratch[8 * 4 * 9];    //  4608 B  pass1 partials [ks][b4][quad], pitch 9
    float  recF[2 * 4 * HS];      //  1024 B  [g][b4][h]
    float  hyStage[2 * 4 * HS];   //  1024 B  [g][b4][h]
    u64    mbar[4];               //    32 B  wbar0, wbar1, hybar0, hybar1
};                                 // ~105 KB -> 2 CTAs/SM

__device__ __forceinline__ uint32_t smem_u32(const void* p) {
    uint32_t a;
    asm("{ .reg .u64 t; cvta.to.shared.u64 t, %1; cvt.u32.u64 %0, t; }"
        : "=r"(a) : "l"(p));
    return a;
}
__device__ __forceinline__ uint32_t mapa_u32(uint32_t a, uint32_t r) {
    uint32_t d;
    asm("mapa.shared::cluster.u32 %0, %1, %2;" : "=r"(d) : "r"(a), "r"(r));
    return d;
}
__device__ __forceinline__ void st_cluster_u64(uint32_t a, u64 v) {
    asm volatile("st.shared::cluster.u64 [%0], %1;" :: "r"(a), "l"(v) : "memory");
}
__device__ __forceinline__ void st_cluster_v4(uint32_t a, float4 v) {
    asm volatile("st.shared::cluster.v4.f32 [%0], {%1, %2, %3, %4};"
                 :: "r"(a), "f"(v.x), "f"(v.y), "f"(v.z), "f"(v.w) : "memory");
}
__device__ __forceinline__ uint32_t ctarank() {
    uint32_t r;
    asm("mov.u32 %0, %%cluster_ctarank;" : "=r"(r));
    return r;
}
__device__ __forceinline__ void fma2(u64& d, u64 a, u64 b) {
    asm("fma.rn.f32x2 %0, %1, %2, %0;" : "+l"(d) : "l"(a), "l"(b));
}
__device__ __forceinline__ float2 unpk(u64 v) {
    float2 f;
    asm("mov.b64 {%0, %1}, %2;" : "=f"(f.x), "=f"(f.y) : "l"(v));
    return f;
}
__device__ __forceinline__ u64 dup_f32(float v) {
    u64 d;
    asm("mov.b64 %0, {%1, %1};" : "=l"(d) : "f"(v));
    return d;
}
__device__ __forceinline__ u64 pack2(float a, float b) {
    u64 d;
    asm("mov.b64 %0, {%1, %2};" : "=l"(d) : "f"(a), "f"(b));
    return d;
}
// tanh(x) = 1 - 2/(e^{2x}+1), ex2/rcp approx. ~1e-6 rel err.
__device__ __forceinline__ float ftanh(float x) {
    float e, r;
    asm("ex2.approx.f32 %0, %1;" : "=f"(e) : "f"(x * 2.885390082f));
    asm("rcp.approx.f32 %0, %1;" : "=f"(r) : "f"(e + 1.0f));
    return fmaf(-2.0f, r, 1.0f);
}
#define CLUSTER_SYNC() do { \
    asm volatile("barrier.cluster.arrive.aligned;" ::: "memory"); \
    asm volatile("barrier.cluster.wait.aligned;" ::: "memory"); \
} while (0)

#define MBARRIER_INIT(addr, count) \
    asm volatile("mbarrier.init.shared.b64 [%0], %1;" \
                 :: "r"((uint32_t)(addr)), "r"((uint32_t)(count)) : "memory")

// remote arrive with release at cluster scope (covers this thread's prior
// st.shared::cluster stores)
#define MBAR_ARRIVE(raddr) \
    asm volatile("mbarrier.arrive.release.cluster.shared::cluster.b64 _, [%0];" \
                 :: "r"(raddr) : "memory")

// wait on own barrier for given phase parity, acquiring cluster-scope stores
#define MBAR_WAIT(addr, par) do {                                            \
    uint32_t _m = (addr), _p = (uint32_t)(par), _d;                          \
    asm volatile("{\n\t.reg .pred P;\n\t"                                    \
        "mbarrier.try_wait.parity.acquire.cluster.shared::cta.b64 P, [%1], %2;\n\t" \
        "selp.b32 %0, 1, 0, P;\n\t}"                                         \
        : "=r"(_d) : "r"(_m), "r"(_p) : "memory");                           \
    if (!_d) {                                                               \
        asm volatile("{\n\t.reg .pred P;\n"                                  \
            "WL%=:\n\t"                                                      \
            "mbarrier.try_wait.parity.acquire.cluster.shared::cta.b64 P, [%0], %1, 0x989680;\n\t" \
            "@P bra.uni WD%=;\n\t"                                           \
            "bra.uni WL%=;\n\t"                                              \
            "WD%=:\n\t}"                                                     \
            :: "r"(_m), "r"(_p) : "memory");                                 \
    }                                                                        \
} while (0)

// ===================== prelude: i2h_all = tanh(x @ x2h) -> out ==============
#define PRE_CTAS 512
#define XDP 130
__global__ void __launch_bounds__(512, 1)
i2h_kernel(const float* __restrict__ x, const float* __restrict__ x2h,
           float* __restrict__ out)
{
    extern __shared__ float ps[];
    float* W2 = ps;
    float* xd = ps + 64 * 512;
    const int t = threadIdx.x;

    for (int idx = t; idx < 64 * 512 / 4; idx += 512)
        *reinterpret_cast<float4*>(&W2[idx * 4]) =
            *reinterpret_cast<const float4*>(&x2h[idx * 4]);

    const int hg = t >> 3;
    const int rq = t & 7;
    const long r0 = (long)blockIdx.x * 256;

    for (int tile = 0; tile < 16; ++tile) {
        __syncthreads();
        #pragma unroll
        for (int rr = 0; rr < 2; ++rr) {
            int e = t + rr * 512;
            int row = e >> 6, i = e & 63;
            float v = x[(r0 + tile * 16 + row) * 64 + i];
            *reinterpret_cast<float2*>(&xd[row * XDP + i * 2]) = make_float2(v, v);
        }
        __syncthreads();

        u64 acc[2][4];
        #pragma unroll
        for (int a = 0; a < 2; ++a)
            #pragma unroll
            for (int b = 0; b < 4; ++b) acc[a][b] = 0ull;

        const float* xe_p = &xd[(rq * 2 + 0) * XDP];
        const float* xo_p = &xd[(rq * 2 + 1) * XDP];
        #pragma unroll 8
        for (int i = 0; i < 64; ++i) {
            ulonglong2 wA = *reinterpret_cast<const ulonglong2*>(&W2[i * 512 + hg * 8]);
            ulonglong2 wB = *reinterpret_cast<const ulonglong2*>(&W2[i * 512 + hg * 8 + 4]);
            u64 xe = *reinterpret_cast<const u64*>(&xe_p[i * 2]);
            u64 xo = *reinterpret_cast<const u64*>(&xo_p[i * 2]);
            fma2(acc[0][0], wA.x, xe); fma2(acc[0][1], wA.y, xe);
            fma2(acc[0][2], wB.x, xe); fma2(acc[0][3], wB.y, xe);
            fma2(acc[1][0], wA.x, xo); fma2(acc[1][1], wA.y, xo);
            fma2(acc[1][2], wB.x, xo); fma2(acc[1][3], wB.y, xo);
        }
        #pragma unroll
        for (int rr = 0; rr < 2; ++rr) {
            long row = r0 + tile * 16 + rq * 2 + rr;
            float4 o0, o1; float2 f;
            f = unpk(acc[rr][0]); o0.x = ftanh(f.x); o0.y = ftanh(f.y);
            f = unpk(acc[rr][1]); o0.z = ftanh(f.x); o0.w = ftanh(f.y);
            f = unpk(acc[rr][2]); o1.x = ftanh(f.x); o1.y = ftanh(f.y);
            f = unpk(acc[rr][3]); o1.z = ftanh(f.x); o1.w = ftanh(f.y);
            *reinterpret_cast<float4*>(&out[row * 512 + hg * 8])     = o0;
            *reinterpret_cast<float4*>(&out[row * 512 + hg * 8 + 4]) = o1;
        }
    }
}

// ===================== main recurrence (mbarrier-pipelined groups) ==========
__global__ void __launch_bounds__(THREADS, 2)
piron_kernel(const float* __restrict__ h2h,
             const float* __restrict__ bias,
             const float* __restrict__ gamma,
             const float* __restrict__ eps,
             float* outp,
             int out_size)
{
    extern __shared__ Smem smem[];
    Smem& S = smem[0];
    const int      t       = threadIdx.x;
    const uint32_t rank    = ctarank();
    const int      cluster = blockIdx.x / CSZ;
    const int      h0      = (int)rank * HS;

    // ---- init: W with swizzle slot = gq ^ SWZ(k) ----
    for (int idx = t; idx < 512 * 8; idx += THREADS) {
        int k = idx >> 3, gq = idx & 7;
        float4 v = *reinterpret_cast<const float4*>(h2h + (size_t)k * N_HID + h0 + gq * 4);
        S.W[(k << 3) | (gq ^ SWZ(k))] = v;
    }
    for (int idx = t; idx < BC * HYF_P; idx += THREADS) S.hy_full[idx] = 0.f;
    const uint32_t mb = smem_u32(&S.mbar[0]);
    if (t == 0) {
        MBARRIER_INIT(mb + 0,  256);  // wbar0
        MBARRIER_INIT(mb + 8,  256);  // wbar1
        MBARRIER_INIT(mb + 16, 512);  // hybar0
        MBARRIER_INIT(mb + 24, 512);  // hybar1
    }
    __syncthreads();
    CLUSTER_SYNC();   // barriers + zeros visible cluster-wide

    // ---- thread roles ----
    // B: gq quad (8), b4b batch-in-group (4), ks k-split warp (8)
    const int gq  = t & 7;
    const int b4b = (t >> 3) & 3;
    const int ks  = t >> 5;
    // E-own: eg = t>>7, eb4 = (t>>5)&3, h = t&31
    const int eg  = t >> 7;
    const int eb4 = (t >> 5) & 3;
    const int h   = t & 31;

    // ---- persistent per-thread state ----
    const float bs = bias[h0 + h];
    const float gm = gamma[h0 + h];
    const float ep = eps[h0 + h];
    float hy = 0.f, hz = 0.f;

    // D scatter: rows k0=2t, k1=2t+1 -> peer t>>4, kin = 2*(t&15)
    const uint32_t scD = mapa_u32(
        smem_u32(&S.wrecv[(int)rank * 128 + 2 * (t & 15)]), (uint32_t)(t >> 4));
    uint32_t wbarr[2] = { mapa_u32(mb + 0, (uint32_t)(t >> 4)),
                          mapa_u32(mb + 8, (uint32_t)(t >> 4)) };
    // E bcast: unit u = t>>3 of hyStage[g]; peers pa = 2*(t&7), pb = pa+1
    const int u  = t >> 3;
    const int bu = u >> 3, q = u & 7;
    const uint32_t pa = 2u * (uint32_t)(t & 7), pb = pa + 1;
    uint32_t hba[2][2], hybarr[2][2];
    {
        uint32_t l0 = smem_u32(&S.hy_full[(0 * 4 + bu) * HYF_P + h0 + q * 4]);
        uint32_t l1 = smem_u32(&S.hy_full[(1 * 4 + bu) * HYF_P + h0 + q * 4]);
        hba[0][0] = mapa_u32(l0, pa); hba[0][1] = mapa_u32(l0, pb);
        hba[1][0] = mapa_u32(l1, pa); hba[1][1] = mapa_u32(l1, pb);
        hybarr[0][0] = mapa_u32(mb + 16, pa); hybarr[0][1] = mapa_u32(mb + 16, pb);
        hybarr[1][0] = mapa_u32(mb + 24, pa); hybarr[1][1] = mapa_u32(mb + 24, pb);
    }
    // out pointer for this thread's owned (batch, h)
    float* po = outp + (size_t)(cluster * BC + eg * 4 + eb4) * SEQ * N_HID + h0 + h;

    const float* scF = reinterpret_cast<const float*>(S.scratch);
    float i2 = po[0];

    for (int step = 0; step < SEQ; ++step) {
        const uint32_t parW = (uint32_t)(step & 1);        // wbar completes this step
        const uint32_t parH = (uint32_t)((step & 1) ^ 1);  // hybar completed prev step

        // ======= pass1/pass2 for each group (pipelined) =======
        #pragma unroll
        for (int g = 0; g < 2; ++g) {
            if (step) MBAR_WAIT(mb + 16 + g * 8, parH);    // hy group g ready

            // B_g: rec partials, 1 batch/thread, k split across warps
            {
                const float* hyb = &S.hy_full[(g * 4 + b4b) * HYF_P + ks * 64];
                const float4* Wp = S.W + (ks << 9);
                u64 a0 = 0, a1 = 0;
                #pragma unroll 8
                for (int j = 0; j < 64; ++j) {
                    ulonglong2 w2 = *reinterpret_cast<const ulonglong2*>(
                        Wp + (j << 3) + (gq ^ SWZ(j)));
                    u64 hv = dup_f32(hyb[j]);
                    fma2(a0, w2.x, hv); fma2(a1, w2.y, hv);
                }
                ulonglong2 s; s.x = a0; s.y = a1;
                *reinterpret_cast<ulonglong2*>(&S.scratch[(ks * 4 + b4b) * 9 + gq]) = s;
            }
            __syncthreads();

            // C_g: reduce 8 k-splits + bias + tanh -> recF[g]
            if (t < 128) {
                int cb = t >> 5, ch = t & 31;
                float v = bs;   // bs corresponds to h = t&31 = ch
                #pragma unroll
                for (int s = 0; s < 8; ++s)
                    v += scF[((s * 4 + cb) * 9 + (ch >> 2)) * 4 + (ch & 3)];
                S.recF[g * 128 + cb * 32 + ch] = ftanh(v);
            }
            __syncthreads();

            // D_g: w partials for rows k0=2t, k1=2t+1, 4 batches; scatter+arrive
            {
                const int k0 = 2 * t, k1 = k0 + 1;
                const float4* W0 = S.W + (k0 << 3);
                const float4* W1 = S.W + (k1 << 3);
                const int s0 = SWZ(k0), s1 = SWZ(k1);
                const float* rg = &S.recF[g * 128];
                u64 a0[4], a1[4];
                #pragma unroll
                for (int bb = 0; bb < 4; ++bb) { a0[bb] = 0ull; a1[bb] = 0ull; }
                #pragma unroll
                for (int gg = 0; gg < 8; ++gg) {
                    ulonglong2 w0 = *reinterpret_cast<const ulonglong2*>(W0 + (gg ^ s0));
                    ulonglong2 w1 = *reinterpret_cast<const ulonglong2*>(W1 + (gg ^ s1));
                    #pragma unroll
                    for (int bb = 0; bb < 4; ++bb) {
                        ulonglong2 r2 = *reinterpret_cast<const ulonglong2*>(
                            rg + bb * 32 + gg * 4);
                        fma2(a0[bb], w0.x, r2.x); fma2(a0[bb], w0.y, r2.y);
                        fma2(a1[bb], w1.x, r2.x); fma2(a1[bb], w1.y, r2.y);
                    }
                }
                #pragma unroll
                for (int bb = 0; bb < 4; ++bb) {
                    float2 f0 = unpk(a0[bb]), f1 = unpk(a1[bb]);
                    st_cluster_u64(scD + (uint32_t)(g * 8192 + bb * 128),
                                   pack2(f0.x + f0.y, f1.x + f1.y));
                }
                MBAR_ARRIVE(wbarr[g]);
            }
        }

        // ======= update + hy broadcast for each group =======
        #pragma unroll
        for (int g = 0; g < 2; ++g) {
            if (eg == g) {
                MBAR_WAIT(mb + g * 8, parW);   // all w partials for group g landed
                float w = 0.f;
                #pragma unroll
                for (int src = 0; src < CSZ; ++src)
                    w += S.wrecv[g * 2048 + src * 128 + eb4 * 32 + h];
                hz += DT_C * (i2 - w - gm * hy - ep * hz);
                hy += DT_C * hz;
                po[(size_t)step * N_HID] = hy;
                if (step + 1 < SEQ) i2 = po[(size_t)(step + 1) * N_HID];
                S.hyStage[g * 128 + eb4 * 32 + h] = hy;
            }
            __syncthreads();
            // broadcast group's hy slice to 2 peers + arrive
            {
                float4 v = *reinterpret_cast<const float4*>(
                    &S.hyStage[g * 128 + u * 4]);
                st_cluster_v4(hba[g][0], v);
                st_cluster_v4(hba[g][1], v);
                MBAR_ARRIVE(hybarr[g][0]);
                MBAR_ARRIVE(hybarr[g][1]);
            }
        }
    }

    // FIX (R15 crash): no CTA may exit while peers' st.shared::cluster /
    // mbarrier.arrive targeting its SMEM are still in flight. The hot loop
    // no longer has cluster barriers, so fence the whole cluster once here.
    CLUSTER_SYNC();

    // ---- final hy appended after states ----
    if (out_size >= BATCH * SEQ * N_HID + BATCH * N_HID) {
        outp[(size_t)BATCH * SEQ * N_HID +
             (size_t)(cluster * BC + eg * 4 + eb4) * N_HID + h0 + h] = hy;
    }
}

extern "C" void kernel_launch(void* const* d_in, const int* in_sizes, int n_in,
                              void* d_out, int out_size) {
    (void)in_sizes; (void)n_in;
    const float* x     = (const float*)d_in[0];
    const float* x2h   = (const float*)d_in[1];
    const float* h2h   = (const float*)d_in[2];
    const float* bias  = (const float*)d_in[3];
    const float* gamma = (const float*)d_in[4];
    const float* eps   = (const float*)d_in[5];
    float* out = (float*)d_out;

    const int pre_smem = (64 * 512 + 16 * XDP) * 4;
    cudaFuncSetAttribute(i2h_kernel,
                         cudaFuncAttributeMaxDynamicSharedMemorySize, pre_smem);
    cudaFuncSetAttribute(piron_kernel,
                         cudaFuncAttributeMaxDynamicSharedMemorySize,
                         (int)sizeof(Smem));
    cudaFuncSetAttribute(piron_kernel,
                         cudaFuncAttributeNonPortableClusterSizeAllowed, 1);

    i2h_kernel<<<PRE_CTAS, 512, pre_smem>>>(x, x2h, out);

    // 16 clusters x 16 CTAs = 256 CTAs -> 2 CTAs/SM co-resident
    cudaLaunchConfig_t cfg = {};
    cfg.gridDim  = dim3((BATCH / BC) * CSZ, 1, 1);
    cfg.blockDim = dim3(THREADS, 1, 1);
    cfg.dynamicSmemBytes = sizeof(Smem);
    cudaLaunchAttribute attrs[1];
    attrs[0].id = cudaLaunchAttributeClusterDimension;
    attrs[0].val.clusterDim = {CSZ, 1, 1};
    cfg.attrs = attrs;
    cfg.numAttrs = 1;
    cudaLaunchKernelEx(&cfg, piron_kernel, h2h, bias, gamma, eps, out, out_size);
}

// round 17
// speedup vs baseline: 1.6525x; 1.6525x over previous
#include <cuda_runtime.h>
#include <cstdint>

typedef unsigned long long u64;

#define N_INP   64
#define N_HID   512
#define BATCH   128
#define SEQ     1024
#define DT_C    0.042f
#define CSZ     16      // CTAs per cluster
#define BC      8       // batches per cluster
#define HS      32      // hidden slice per CTA
#define THREADS 256
#define HYF_P   516     // hy_full row pitch (floats)

struct __align__(16) Smem {
    float4 W[512 * 8];            // 65536 B  h2h[:,slice], slot = gq ^ (k&7)
    float  hy_full[BC * HYF_P];   // 16512 B  all-gathered hy, [b][k]
    float  wrecv[CSZ * BC * HS];  // 16384 B  [src][b][kin]
    float4 scratch[8 * 8 * 9];    //  9216 B  pass1 partials [ks][b][quad], pitch 9
    float  recF[BC * HS];         //  1024 B  rec[b][h]
    float  hyStage[BC * HS];      //  1024 B  staging for v4 broadcast
    u64    hybar;                 //     8 B  hy all-gather barrier (count 16)
};                                 // ~110 KB -> 2 CTAs/SM

__device__ __forceinline__ uint32_t smem_u32(const void* p) {
    uint32_t a;
    asm("{ .reg .u64 t; cvta.to.shared.u64 t, %1; cvt.u32.u64 %0, t; }"
        : "=r"(a) : "l"(p));
    return a;
}
__device__ __forceinline__ uint32_t mapa_u32(uint32_t a, uint32_t r) {
    uint32_t d;
    asm("mapa.shared::cluster.u32 %0, %1, %2;" : "=r"(d) : "r"(a), "r"(r));
    return d;
}
__device__ __forceinline__ void st_cluster_f32(uint32_t a, float v) {
    asm volatile("st.shared::cluster.f32 [%0], %1;" :: "r"(a), "f"(v) : "memory");
}
__device__ __forceinline__ void st_cluster_v4(uint32_t a, float4 v) {
    asm volatile("st.shared::cluster.v4.f32 [%0], {%1, %2, %3, %4};"
                 :: "r"(a), "f"(v.x), "f"(v.y), "f"(v.z), "f"(v.w) : "memory");
}
__device__ __forceinline__ uint32_t ctarank() {
    uint32_t r;
    asm("mov.u32 %0, %%cluster_ctarank;" : "=r"(r));
    return r;
}
__device__ __forceinline__ void fma2(u64& d, u64 a, u64 b) {
    asm("fma.rn.f32x2 %0, %1, %2, %0;" : "+l"(d) : "l"(a), "l"(b));
}
__device__ __forceinline__ float2 unpk(u64 v) {
    float2 f;
    asm("mov.b64 {%0, %1}, %2;" : "=f"(f.x), "=f"(f.y) : "l"(v));
    return f;
}
__device__ __forceinline__ u64 dup_f32(float v) {
    u64 d;
    asm("mov.b64 %0, {%1, %1};" : "=l"(d) : "f"(v));
    return d;
}
// tanh(x) = 1 - 2/(e^{2x}+1), ex2/rcp approx. ~1e-6 rel err.
__device__ __forceinline__ float ftanh(float x) {
    float e, r;
    asm("ex2.approx.f32 %0, %1;" : "=f"(e) : "f"(x * 2.885390082f));
    asm("rcp.approx.f32 %0, %1;" : "=f"(r) : "f"(e + 1.0f));
    return fmaf(-2.0f, r, 1.0f);
}
#define CLUSTER_SYNC() do { \
    asm volatile("barrier.cluster.arrive.aligned;" ::: "memory"); \
    asm volatile("barrier.cluster.wait.aligned;" ::: "memory"); \
} while (0)

#define MBARRIER_INIT(addr, count) \
    asm volatile("mbarrier.init.shared.b64 [%0], %1;" \
                 :: "r"((uint32_t)(addr)), "r"((uint32_t)(count)) : "memory")

#define FENCE_ACQ_REL_CLUSTER() \
    asm volatile("fence.acq_rel.cluster;" ::: "memory")

#define MBAR_ARRIVE_REMOTE(raddr) \
    asm volatile("mbarrier.arrive.release.cluster.shared::cluster.b64 _, [%0];" \
                 :: "r"(raddr) : "memory")

#define MBAR_WAIT(addr, par) do {                                            \
    uint32_t _m = (addr), _p = (uint32_t)(par), _d;                          \
    asm volatile("{\n\t.reg .pred P;\n\t"                                    \
        "mbarrier.try_wait.parity.acquire.cluster.shared::cta.b64 P, [%1], %2;\n\t" \
        "selp.b32 %0, 1, 0, P;\n\t}"                                         \
        : "=r"(_d) : "r"(_m), "r"(_p) : "memory");                           \
    if (!_d) {                                                               \
        asm volatile("{\n\t.reg .pred P;\n"                                  \
            "WL%=:\n\t"                                                      \
            "mbarrier.try_wait.parity.acquire.cluster.shared::cta.b64 P, [%0], %1, 0x989680;\n\t" \
            "@P bra.uni WD%=;\n\t"                                           \
            "bra.uni WL%=;\n\t"                                              \
            "WD%=:\n\t}"                                                     \
            :: "r"(_m), "r"(_p) : "memory");                                 \
    }                                                                        \
} while (0)

// ===================== prelude: i2h_all = tanh(x @ x2h) -> out ==============
#define PRE_CTAS 512
#define XDP 130
__global__ void __launch_bounds__(512, 1)
i2h_kernel(const float* __restrict__ x, const float* __restrict__ x2h,
           float* __restrict__ out)
{
    extern __shared__ float ps[];
    float* W2 = ps;
    float* xd = ps + 64 * 512;
    const int t = threadIdx.x;

    for (int idx = t; idx < 64 * 512 / 4; idx += 512)
        *reinterpret_cast<float4*>(&W2[idx * 4]) =
            *reinterpret_cast<const float4*>(&x2h[idx * 4]);

    const int hg = t >> 3;
    const int rq = t & 7;
    const long r0 = (long)blockIdx.x * 256;

    for (int tile = 0; tile < 16; ++tile) {
        __syncthreads();
        #pragma unroll
        for (int rr = 0; rr < 2; ++rr) {
            int e = t + rr * 512;
            int row = e >> 6, i = e & 63;
            float v = x[(r0 + tile * 16 + row) * 64 + i];
            *reinterpret_cast<float2*>(&xd[row * XDP + i * 2]) = make_float2(v, v);
        }
        __syncthreads();

        u64 acc[2][4];
        #pragma unroll
        for (int a = 0; a < 2; ++a)
            #pragma unroll
            for (int b = 0; b < 4; ++b) acc[a][b] = 0ull;

        const float* xe_p = &xd[(rq * 2 + 0) * XDP];
        const float* xo_p = &xd[(rq * 2 + 1) * XDP];
        #pragma unroll 8
        for (int i = 0; i < 64; ++i) {
            ulonglong2 wA = *reinterpret_cast<const ulonglong2*>(&W2[i * 512 + hg * 8]);
            ulonglong2 wB = *reinterpret_cast<const ulonglong2*>(&W2[i * 512 + hg * 8 + 4]);
            u64 xe = *reinterpret_cast<const u64*>(&xe_p[i * 2]);
            u64 xo = *reinterpret_cast<const u64*>(&xo_p[i * 2]);
            fma2(acc[0][0], wA.x, xe); fma2(acc[0][1], wA.y, xe);
            fma2(acc[0][2], wB.x, xe); fma2(acc[0][3], wB.y, xe);
            fma2(acc[1][0], wA.x, xo); fma2(acc[1][1], wA.y, xo);
            fma2(acc[1][2], wB.x, xo); fma2(acc[1][3], wB.y, xo);
        }
        #pragma unroll
        for (int rr = 0; rr < 2; ++rr) {
            long row = r0 + tile * 16 + rq * 2 + rr;
            float4 o0, o1; float2 f;
            f = unpk(acc[rr][0]); o0.x = ftanh(f.x); o0.y = ftanh(f.y);
            f = unpk(acc[rr][1]); o0.z = ftanh(f.x); o0.w = ftanh(f.y);
            f = unpk(acc[rr][2]); o1.x = ftanh(f.x); o1.y = ftanh(f.y);
            f = unpk(acc[rr][3]); o1.z = ftanh(f.x); o1.w = ftanh(f.y);
            *reinterpret_cast<float4*>(&out[row * 512 + hg * 8])     = o0;
            *reinterpret_cast<float4*>(&out[row * 512 + hg * 8 + 4]) = o1;
        }
    }
}

// ===================== main recurrence (16-CTA cluster, 2 CTA/SM) ===========
__global__ void __launch_bounds__(THREADS, 2)
piron_kernel(const float* __restrict__ h2h,
             const float* __restrict__ bias,
             const float* __restrict__ gamma,
             const float* __restrict__ eps,
             float* outp,
             int out_size)
{
    extern __shared__ Smem smem[];
    Smem& S = smem[0];
    const int      t       = threadIdx.x;
    const uint32_t rank    = ctarank();
    const int      cluster = blockIdx.x / CSZ;
    const int      h0      = (int)rank * HS;

    // ---- init: W swizzled (quad gq of row k at slot gq^(k&7)) ----
    for (int idx = t; idx < 512 * 8; idx += THREADS) {
        int k = idx >> 3, gq = idx & 7;
        float4 v = *reinterpret_cast<const float4*>(h2h + (size_t)k * N_HID + h0 + gq * 4);
        S.W[(k << 3) | (gq ^ (k & 7))] = v;
    }
    for (int idx = t; idx < BC * HYF_P; idx += THREADS) S.hy_full[idx] = 0.f;
    const uint32_t mb = smem_u32(&S.hybar);
    if (t == 0) MBARRIER_INIT(mb, 16);   // one arrive per source CTA
    __syncthreads();
    CLUSTER_SYNC();

    // ---- thread roles ----
    // B (pass1): gq quad, bq batch-pair, ks = warp = k-split of 64
    const int gq = t & 7;
    const int bq = (t >> 3) & 3;
    const int ks = t >> 5;
    // C/E: b = t>>5 batch, h = t&31
    const int b = t >> 5;
    const int h = t & 31;

    // ---- persistent per-thread state (registers) ----
    const float bs = bias[h0 + h];
    const float gm = gamma[h0 + h];
    const float ep = eps[h0 + h];
    float hy = 0.f, hz = 0.f;

    // D scatter bases: rows k0=t (peer t>>5), k1=t+256 (peer (t>>5)+8); kin=t&31
    const uint32_t sc_loc = smem_u32(&S.wrecv[(int)rank * (BC * HS) + (t & 31)]);
    const uint32_t sc0 = mapa_u32(sc_loc, (uint32_t)(t >> 5));
    const uint32_t sc1 = mapa_u32(sc_loc, (uint32_t)(t >> 5) + 8);
    // E broadcast: unit = t&63 covers float4 of hyStage; peers (t>>6)*4 + p
    const int unit = t & 63;
    uint32_t hbb[4];
    {
        int bu = unit >> 3, q = unit & 7;
        uint32_t loc = smem_u32(&S.hy_full[bu * HYF_P + h0 + q * 4]);
        #pragma unroll
        for (int p = 0; p < 4; ++p)
            hbb[p] = mapa_u32(loc, (uint32_t)((t >> 6) * 4 + p));
    }
    // hy-barrier arrive address: thread t<16 arrives at peer t's hybar
    const uint32_t hybar_peer = mapa_u32(mb, (uint32_t)(t & 15));
    // out pointer for this thread's (b, h)
    float* po = outp + (size_t)(cluster * BC + b) * SEQ * N_HID + h0 + h;

    const float* scF = reinterpret_cast<const float*>(S.scratch);

    for (int step = 0; step < SEQ; ++step) {
        // wait for all 16 CTAs' hy broadcasts of the previous step
        if (step) MBAR_WAIT(mb, (uint32_t)((step - 1) & 1));

        // i2h prefetch (consumed in E)
        float i2 = po[(size_t)step * N_HID];

        // ---- B: pass1 partials; warp ks owns k = ks*64 + j ----
        {
            const float* hyb0 = &S.hy_full[(2 * bq + 0) * HYF_P + ks * 64];
            const float* hyb1 = &S.hy_full[(2 * bq + 1) * HYF_P + ks * 64];
            const float4* Wp = S.W + (ks << 9);   // ks*64 rows * 8 quads
            u64 a00 = 0, a01 = 0, a10 = 0, a11 = 0;
            #pragma unroll 8
            for (int j = 0; j < 64; ++j) {
                // (ks*64 + j) & 7 == j & 7
                ulonglong2 w2 = *reinterpret_cast<const ulonglong2*>(
                    Wp + (j << 3) + (gq ^ (j & 7)));
                u64 h0v = dup_f32(hyb0[j]);
                u64 h1v = dup_f32(hyb1[j]);
                fma2(a00, w2.x, h0v); fma2(a01, w2.y, h0v);
                fma2(a10, w2.x, h1v); fma2(a11, w2.y, h1v);
            }
            ulonglong2 s;
            int r0 = (ks * 8 + 2 * bq) * 9 + gq;
            s.x = a00; s.y = a01;
            *reinterpret_cast<ulonglong2*>(&S.scratch[r0]) = s;
            s.x = a10; s.y = a11;
            *reinterpret_cast<ulonglong2*>(&S.scratch[r0 + 9]) = s;
        }
        __syncthreads();

        // ---- C: reduce 8 k-splits + bias + tanh -> recF ----
        {
            float v = bs;
            #pragma unroll
            for (int s = 0; s < 8; ++s)
                v += scF[((s * 8 + b) * 9 + (h >> 2)) * 4 + (h & 3)];
            S.recF[b * HS + h] = ftanh(v);
        }
        __syncthreads();

        // ---- D: pass2, thread owns rows k0=t, k1=t+256 for all 8 b ----
        {
            const float4* W0 = S.W + (t << 3);
            const float4* W1 = S.W + ((t + 256) << 3);
            const int swz = t & 7;
            u64 acc0[8], acc1[8];
            #pragma unroll
            for (int bb = 0; bb < 8; ++bb) { acc0[bb] = 0ull; acc1[bb] = 0ull; }
            #pragma unroll
            for (int gg = 0; gg < 8; ++gg) {
                int slot = gg ^ swz;
                ulonglong2 w0 = *reinterpret_cast<const ulonglong2*>(W0 + slot);
                ulonglong2 w1 = *reinterpret_cast<const ulonglong2*>(W1 + slot);
                #pragma unroll
                for (int bb = 0; bb < 8; ++bb) {
                    ulonglong2 r2 = *reinterpret_cast<const ulonglong2*>(
                        &S.recF[bb * HS + gg * 4]);
                    fma2(acc0[bb], w0.x, r2.x); fma2(acc0[bb], w0.y, r2.y);
                    fma2(acc1[bb], w1.x, r2.x); fma2(acc1[bb], w1.y, r2.y);
                }
            }
            #pragma unroll
            for (int bb = 0; bb < 8; ++bb) {
                float2 f0 = unpk(acc0[bb]);
                float2 f1 = unpk(acc1[bb]);
                st_cluster_f32(sc0 + (uint32_t)(bb * HS * 4), f0.x + f0.y);
                st_cluster_f32(sc1 + (uint32_t)(bb * HS * 4), f1.x + f1.y);
            }
        }
        CLUSTER_SYNC();   // sync1: scatter complete everywhere (also fences
                          // E's upcoming hy_full writes against B's reads)

        // ---- E: reduce 16 partials, update state, emit, stage hy ----
        {
            float w = 0.f;
            #pragma unroll
            for (int src = 0; src < CSZ; ++src)
                w += S.wrecv[src * (BC * HS) + b * HS + h];
            hz += DT_C * (i2 - w - gm * hy - ep * hz);
            hy += DT_C * hz;
            po[(size_t)step * N_HID] = hy;
            S.hyStage[b * HS + h] = hy;
        }
        __syncthreads();

        // ---- broadcast hy (v4) into all 16 CTAs' hy_full ----
        {
            float4 v = *reinterpret_cast<const float4*>(&S.hyStage[unit * 4]);
            #pragma unroll
            for (int p = 0; p < 4; ++p) st_cluster_v4(hbb[p], v);
        }
        __syncthreads();          // all 256 threads' broadcast stores issued
        if (t < 16) {
            FENCE_ACQ_REL_CLUSTER();        // cumulative: covers CTA's stores
            MBAR_ARRIVE_REMOTE(hybar_peer); // signal peer t: my slice arrived
        }
    }

    // No CTA may exit while peers' cluster stores / arrives into its SMEM
    // are in flight (R15 lesson).
    CLUSTER_SYNC();

    // ---- final hy appended after states ----
    if (out_size >= BATCH * SEQ * N_HID + BATCH * N_HID) {
        outp[(size_t)BATCH * SEQ * N_HID +
             (size_t)(cluster * BC + b) * N_HID + h0 + h] = hy;
    }
}

extern "C" void kernel_launch(void* const* d_in, const int* in_sizes, int n_in,
                              void* d_out, int out_size) {
    (void)in_sizes; (void)n_in;
    const float* x     = (const float*)d_in[0];
    const float* x2h   = (const float*)d_in[1];
    const float* h2h   = (const float*)d_in[2];
    const float* bias  = (const float*)d_in[3];
    const float* gamma = (const float*)d_in[4];
    const float* eps   = (const float*)d_in[5];
    float* out = (float*)d_out;

    const int pre_smem = (64 * 512 + 16 * XDP) * 4;
    cudaFuncSetAttribute(i2h_kernel,
                         cudaFuncAttributeMaxDynamicSharedMemorySize, pre_smem);
    cudaFuncSetAttribute(piron_kernel,
                         cudaFuncAttributeMaxDynamicSharedMemorySize,
                         (int)sizeof(Smem));
    cudaFuncSetAttribute(piron_kernel,
                         cudaFuncAttributeNonPortableClusterSizeAllowed, 1);

    i2h_kernel<<<PRE_CTAS, 512, pre_smem>>>(x, x2h, out);

    // 16 clusters x 16 CTAs = 256 CTAs -> 2 CTAs/SM co-resident
    cudaLaunchConfig_t cfg = {};
    cfg.gridDim  = dim3((BATCH / BC) * CSZ, 1, 1);
    cfg.blockDim = dim3(THREADS, 1, 1);
    cfg.dynamicSmemBytes = sizeof(Smem);
    cudaLaunchAttribute attrs[1];
    attrs[0].id = cudaLaunchAttributeClusterDimension;
    attrs[0].val.clusterDim = {CSZ, 1, 1};
    cfg.attrs = attrs;
    cfg.numAttrs = 1;
    cudaLaunchKernelEx(&cfg, piron_kernel, h2h, bias, gamma, eps, out, out_size);
}